// round 13
// baseline (speedup 1.0000x reference)
#include <cuda_runtime.h>

// LDR toeplitz-displacement layer via FFT with 2-term real packing everywhere.
//   Hf = fft(D*H); Gf = fft(G); Xf = ifft(conj(D)*x)
//   t = D*fft(Hf.Xf) is REAL => pack two chain terms: z = u1 + i*u2,
//   W = fft(D.fft(z)) = Tf1 + i*Tf2 (Tf Hermitian), unpack via reversed read.
//   out = Re(ifft(sum Gf.Tf)) / (2N).
// Prep (NT=256, 128 blk): packs PAIRS of real rows per FFT (sigma unpack).
// Main (NT=512, 128 blk): warps 0-7 run chains 0-3, warps 8-15 run chains 4-7,
//   separate buffers + smem accumulators, SHARED barriers (24 phases, 16 warps
//   of latency hiding). Final: radix-8 IFFT with all 512 threads.
// FFT: radix-16 Stockham, 2 smem exchanges, in-place digit-swapped DFT16.
// Twiddles: hybrid w1..w8 live, k>8 via w8*w_{k-8} (<=2-deep chains).

#define NN    4096
#define CIN   4
#define COUT  4
#define RANK  4
#define BATCH 32

#define NTP   256     // prep threads
#define NTM   512     // main threads
#define PIDX16(i) ((i) + ((i) >> 4))
#define NPAD16 4352
#define PREP_SMEM ((2 * NPAD16 + 256) * (int)sizeof(float2))
// main: h0b0 h0b1 h1b0 h1b1 + accsA[NN] + accsB[NN] + W[512]
#define MAIN_SMEM ((4 * NPAD16 + 2 * NN + 512) * (int)sizeof(float2))

#define SW16(m) ((((m) & 3) << 2) | ((m) >> 2))

__device__ float2 g_Hf[CIN*COUT*RANK][NN];   // 2 MB
__device__ float2 g_Gf[CIN*COUT*RANK][NN];   // 2 MB
__device__ float2 g_Xf[CIN*BATCH][NN];       // 4 MB

__device__ __forceinline__ float2 cmul(float2 a, float2 b) {
    return make_float2(a.x*b.x - a.y*b.y, a.x*b.y + a.y*b.x);
}
__device__ __forceinline__ float2 cadd(float2 a, float2 b) { return make_float2(a.x+b.x, a.y+b.y); }
__device__ __forceinline__ float2 csub(float2 a, float2 b) { return make_float2(a.x-b.x, a.y-b.y); }

// ============ radix-16 machinery (in-place digit-swapped DFT16) =============

template<int INV>
__device__ __forceinline__ void dft4ip(float2& a, float2& b, float2& c, float2& d) {
    float2 t0 = cadd(a,c), t1 = csub(a,c), t2 = cadd(b,d), bd = csub(b,d);
    float2 t3 = INV ? make_float2(-bd.y, bd.x) : make_float2(bd.y, -bd.x);
    a = cadd(t0,t2); b = cadd(t1,t3); c = csub(t0,t2); d = csub(t1,t3);
}

template<int INV>
__device__ __forceinline__ void tw16ip(float2 v[16]) {
    const float C1 = 0.92387953251128675613f;
    const float S1 = 0.38268343236508977172f;
    const float CC = 0.70710678118654752440f;
#define TW(m, c, s) v[m] = cmul(v[m], make_float2((c), INV ? (s) : -(s)))
    TW(5,  C1,  S1);
    TW(6,  CC,  CC);
    TW(7,  S1,  C1);
    TW(9,  CC,  CC);
    TW(10, 0.0f, 1.0f);
    TW(11, -CC, CC);
    TW(13, S1,  C1);
    TW(14, -CC, CC);
    TW(15, -C1, -S1);
#undef TW
}

template<int INV>
__device__ __forceinline__ void dft16A(float2 v[16]) {
#pragma unroll
    for (int n0 = 0; n0 < 4; ++n0) dft4ip<INV>(v[n0], v[n0+4], v[n0+8], v[n0+12]);
    tw16ip<INV>(v);
#pragma unroll
    for (int q = 0; q < 4; ++q) dft4ip<INV>(v[4*q], v[4*q+1], v[4*q+2], v[4*q+3]);
}

template<int INV>
__device__ __forceinline__ void dft16B(float2 v[16]) {
#pragma unroll
    for (int q = 0; q < 4; ++q) dft4ip<INV>(v[4*q], v[4*q+1], v[4*q+2], v[4*q+3]);
    tw16ip<INV>(v);
#pragma unroll
    for (int n0 = 0; n0 < 4; ++n0) dft4ip<INV>(v[n0], v[n0+4], v[n0+8], v[n0+12]);
}

// butterfly + hybrid twiddle scatter: w1..w8 live; k>8 -> (o*w8)*w_{k-8}.
template<int INV, int IN_SWAPPED>
__device__ __forceinline__ void stage_store16(float2 v[16], float2* __restrict__ sb,
                                              const float2* __restrict__ W,
                                              int u, int sshift) {
    if (IN_SWAPPED) dft16B<INV>(v); else dft16A<INV>(v);
    const int s  = 1 << sshift;
    const int k1 = u & ~(s - 1);
    const int base = u + 15 * k1;
    float2 w1 = W[k1];
    if (INV) w1.y = -w1.y;
    const float2 w2 = cmul(w1, w1);
    const float2 w3 = cmul(w2, w1);
    const float2 w4 = cmul(w2, w2);
    const float2 w5 = cmul(w4, w1);
    const float2 w6 = cmul(w4, w2);
    const float2 w7 = cmul(w4, w3);
    const float2 w8 = cmul(w4, w4);
    const float2 wlo[8] = { make_float2(1.0f, 0.0f), w1, w2, w3, w4, w5, w6, w7 };
#pragma unroll
    for (int k = 0; k < 16; ++k) {
        float2 o = IN_SWAPPED ? v[k] : v[SW16(k)];
        if (k >= 8) o = cmul(o, w8);
        if (k & 7)  o = cmul(o, wlo[k & 7]);
        sb[PIDX16(base + k * s)] = o;
    }
}

__device__ __forceinline__ void stage_load16(float2 v[16], const float2* __restrict__ sb, int t) {
#pragma unroll
    for (int k = 0; k < 16; ++k) v[k] = sb[PIDX16(t + 256 * k)];
}

// =================== radix-8 (final IFFT, NT=512 layout) ====================

template<int INV>
__device__ __forceinline__ void bf8(float2 v[8]) {
    const float C = 0.70710678118654752440f;
    float2 e0,e1,e2,e3,o0,o1,o2,o3;
    {
        float2 t0 = cadd(v[0], v[4]);
        float2 t1 = csub(v[0], v[4]);
        float2 t2 = cadd(v[2], v[6]);
        float2 d  = csub(v[2], v[6]);
        float2 t3 = INV ? make_float2(-d.y, d.x) : make_float2(d.y, -d.x);
        e0 = cadd(t0,t2); e1 = cadd(t1,t3); e2 = csub(t0,t2); e3 = csub(t1,t3);
    }
    {
        float2 t0 = cadd(v[1], v[5]);
        float2 t1 = csub(v[1], v[5]);
        float2 t2 = cadd(v[3], v[7]);
        float2 d  = csub(v[3], v[7]);
        float2 t3 = INV ? make_float2(-d.y, d.x) : make_float2(d.y, -d.x);
        o0 = cadd(t0,t2); o1 = cadd(t1,t3); o2 = csub(t0,t2); o3 = csub(t1,t3);
    }
    float2 w1o, w2o, w3o;
    if (!INV) {
        w1o = make_float2(C*(o1.x + o1.y), C*(o1.y - o1.x));
        w2o = make_float2(o2.y, -o2.x);
        w3o = make_float2(C*(o3.y - o3.x), C*(-(o3.x + o3.y)));
    } else {
        w1o = make_float2(C*(o1.x - o1.y), C*(o1.y + o1.x));
        w2o = make_float2(-o2.y, o2.x);
        w3o = make_float2(C*(-(o3.x + o3.y)), C*(o3.x - o3.y));
    }
    v[0] = cadd(e0, o0);  v[4] = csub(e0, o0);
    v[1] = cadd(e1, w1o); v[5] = csub(e1, w1o);
    v[2] = cadd(e2, w2o); v[6] = csub(e2, w2o);
    v[3] = cadd(e3, w3o); v[7] = csub(e3, w3o);
}

template<int INV>
__device__ __forceinline__ void stage_store8(float2 v[8], float2* __restrict__ sb,
                                             const float2* __restrict__ W,
                                             int u, int sshift) {
    bf8<INV>(v);
    const int s  = 1 << sshift;
    const int k1 = u & ~(s - 1);
    const int base = u + 7 * k1;
    float2 w1 = W[k1];
    if (INV) w1.y = -w1.y;
    const float2 w2 = cmul(w1, w1);
    const float2 w3 = cmul(w2, w1);
    const float2 w4 = cmul(w2, w2);
    const float2 w5 = cmul(w3, w2);
    const float2 w6 = cmul(w3, w3);
    const float2 w7 = cmul(w4, w3);
    sb[PIDX16(base)]       = v[0];
    sb[PIDX16(base + s)]   = cmul(v[1], w1);
    sb[PIDX16(base + 2*s)] = cmul(v[2], w2);
    sb[PIDX16(base + 3*s)] = cmul(v[3], w3);
    sb[PIDX16(base + 4*s)] = cmul(v[4], w4);
    sb[PIDX16(base + 5*s)] = cmul(v[5], w5);
    sb[PIDX16(base + 6*s)] = cmul(v[6], w6);
    sb[PIDX16(base + 7*s)] = cmul(v[7], w7);
}

__device__ __forceinline__ void stage_load8(float2 v[8], const float2* __restrict__ sb, int t) {
#pragma unroll
    for (int k = 0; k < 8; ++k) v[k] = sb[PIDX16(t + 512 * k)];
}

// ================ K1: prep, 2 real rows packed per FFT ======================

__global__ void __launch_bounds__(NTP, 2) ldr_prep_kernel(const float* __restrict__ x,
                                                          const float* __restrict__ G,
                                                          const float* __restrict__ H)
{
    extern __shared__ float2 smem2[];
    float2* b0 = smem2;
    float2* b1 = smem2 + NPAD16;
    float2* W  = smem2 + 2 * NPAD16;
    const int tid = threadIdx.x;
    {
        float s, c; sincospif((float)tid * (1.0f / 2048.0f), &s, &c);
        W[tid] = make_float2(c, -s);
    }

    const int bid = blockIdx.x;
    float2 v[16];
    float2 *dst1, *dst2;
    int inv_mode = 0;
    int shift_rev = 1;       // sigma(n) = (shift_rev - n) mod N
    float scale = 0.5f;

    if (bid < 32) {          // Hf rows 2bid, 2bid+1: fft(D * h)
        const float* h1 = H + (2 * bid) * NN;
        const float* h2 = H + (2 * bid + 1) * NN;
#pragma unroll
        for (int k = 0; k < 16; ++k) {
            const int n = tid + 256 * k;
            float s, c; sincospif((float)n * (1.0f / 4096.0f), &s, &c);
            v[k] = cmul(make_float2(c, s), make_float2(h1[n], h2[n]));
        }
        dst1 = g_Hf[2 * bid]; dst2 = g_Hf[2 * bid + 1];
    } else if (bid < 64) {   // Gf rows: fft(g)
        const int r = bid - 32;
        const float* g1 = G + (2 * r) * NN;
        const float* g2 = G + (2 * r + 1) * NN;
#pragma unroll
        for (int k = 0; k < 16; ++k) {
            const int n = tid + 256 * k;
            v[k] = make_float2(g1[n], g2[n]);
        }
        dst1 = g_Gf[2 * r]; dst2 = g_Gf[2 * r + 1];
        shift_rev = 0;       // plain Hermitian
    } else {                 // Xf rows: ifft(conj(D) * x) with 1/N
        const int r = bid - 64;
        const float* x1 = x + (2 * r) * NN;
        const float* x2 = x + (2 * r + 1) * NN;
#pragma unroll
        for (int k = 0; k < 16; ++k) {
            const int n = tid + 256 * k;
            float s, c; sincospif((float)n * (1.0f / 4096.0f), &s, &c);
            v[k] = cmul(make_float2(c, -s), make_float2(x1[n], x2[n]));
        }
        dst1 = g_Xf[2 * r]; dst2 = g_Xf[2 * r + 1];
        inv_mode = 1;
        scale = 0.5f / (float)NN;
    }
    __syncthreads();   // W visible

    if (!inv_mode) {
        stage_store16<0,0>(v, b0, W, tid, 0);
        __syncthreads();
        stage_load16(v, b0, tid);
        stage_store16<0,0>(v, b1, W, tid, 4);
        __syncthreads();
        stage_load16(v, b1, tid);
        dft16A<0>(v);                      // swapped
    } else {
        stage_store16<1,0>(v, b0, W, tid, 0);
        __syncthreads();
        stage_load16(v, b0, tid);
        stage_store16<1,0>(v, b1, W, tid, 4);
        __syncthreads();
        stage_load16(v, b1, tid);
        dft16A<1>(v);                      // swapped
    }

    // unpack exchange through b0
#pragma unroll
    for (int k = 0; k < 16; ++k) b0[PIDX16(tid + 256 * k)] = v[SW16(k)];
    __syncthreads();
#pragma unroll
    for (int k = 0; k < 16; ++k) {
        const int n   = tid + 256 * k;
        const int sg  = (shift_rev - n) & (NN - 1);
        const float2 z  = v[SW16(k)];
        const float2 ws = b0[PIDX16(sg)];
        dst1[n] = make_float2(scale * (z.x + ws.x), scale * (z.y - ws.y));
        dst2[n] = make_float2(scale * (z.y + ws.y), scale * (ws.x - z.x));
    }
}

// ===================== K2: main — thread-half pairing =======================

// e^{i*pi*k/16}
__device__ __constant__ float E16C[16] = { 1.0f, 0.98078528040323044913f,
    0.92387953251128675613f, 0.83146961230254523708f, 0.70710678118654752440f,
    0.55557023301960222474f, 0.38268343236508977172f, 0.19509032201612826785f,
    0.0f, -0.19509032201612826785f, -0.38268343236508977172f,
    -0.55557023301960222474f, -0.70710678118654752440f, -0.83146961230254523708f,
    -0.92387953251128675613f, -0.98078528040323044913f };
__device__ __constant__ float E16S[16] = { 0.0f, 0.19509032201612826785f,
    0.38268343236508977172f, 0.55557023301960222474f, 0.70710678118654752440f,
    0.83146961230254523708f, 0.92387953251128675613f, 0.98078528040323044913f,
    1.0f, 0.98078528040323044913f, 0.92387953251128675613f,
    0.83146961230254523708f, 0.70710678118654752440f, 0.55557023301960222474f,
    0.38268343236508977172f, 0.19509032201612826785f };

// One chain executed by ONE half (256 threads, index ht), barriers block-wide.
// Both halves call this in lockstep with their own buffers/pointers.
__device__ __forceinline__ void do_chain(const float2* __restrict__ hf1,
                                         const float2* __restrict__ hf2,
                                         const float2* __restrict__ gf1,
                                         const float2* __restrict__ gf2,
                                         const float2* __restrict__ xf,
                                         float2* A, float2* B,
                                         float2* __restrict__ accs,
                                         const float2* __restrict__ W,
                                         float2 d0, int ht)
{
    float2 v[16];
#pragma unroll
    for (int k = 0; k < 16; ++k) {
        const int n = ht + 256 * k;
        const float2 xv = xf[n];
        const float2 u1 = cmul(hf1[n], xv);
        const float2 u2 = cmul(hf2[n], xv);
        v[k] = make_float2(u1.x - u2.y, u1.y + u2.x);   // u1 + i*u2
    }
    // fft #1
    stage_store16<0,0>(v, A, W, ht, 0);
    __syncthreads();                                   // bar1
    stage_load16(v, A, ht);
    stage_store16<0,0>(v, B, W, ht, 4);
    __syncthreads();                                   // bar2
    stage_load16(v, B, ht);
    dft16A<0>(v);                                      // swapped
    // D multiply: slot m holds n = ht + 256*SW16(m)
#pragma unroll
    for (int m = 0; m < 16; ++m)
        v[m] = cmul(v[m], cmul(d0, make_float2(E16C[SW16(m)], E16S[SW16(m)])));
    // fft #2 (input swapped)
    stage_store16<0,1>(v, A, W, ht, 0);
    __syncthreads();                                   // bar3
    stage_load16(v, A, ht);
    stage_store16<0,0>(v, B, W, ht, 4);
    __syncthreads();                                   // bar4
    stage_load16(v, B, ht);
    dft16A<0>(v);                                      // swapped
    // Hermitian unpack through A
#pragma unroll
    for (int k = 0; k < 16; ++k) A[PIDX16(ht + 256 * k)] = v[SW16(k)];
    __syncthreads();                                   // bar5
#pragma unroll
    for (int k = 0; k < 16; ++k) {
        const int n   = ht + 256 * k;
        const int rev = (NN - n) & (NN - 1);
        const float2 ws = A[PIDX16(rev)];
        const float2 vk = v[SW16(k)];
        const float2 t1 = make_float2(vk.x + ws.x, vk.y - ws.y);   // 2*Tf1
        const float2 t2 = make_float2(vk.y + ws.y, ws.x - vk.x);   // 2*Tf2
        accs[n] = cadd(accs[n], cadd(cmul(gf1[n], t1), cmul(gf2[n], t2)));
    }
}

__global__ void __launch_bounds__(NTM, 1) ldr_main_kernel(float* __restrict__ out)
{
    extern __shared__ float2 smem2[];
    // per-half buffer pairs
    float2* hb[2][2] = { { smem2,              smem2 + NPAD16     },
                         { smem2 + 2*NPAD16,   smem2 + 3*NPAD16   } };
    float2* accsA = smem2 + 4 * NPAD16;          // half 0 accumulator [NN]
    float2* accsB = accsA + NN;                  // half 1 accumulator [NN]
    float2* W     = accsB + NN;                  // [512]
    const int tid  = threadIdx.x;
    const int half = tid >> 8;
    const int ht   = tid & 255;
    {
        float s, c; sincospif((float)tid * (1.0f / 2048.0f), &s, &c);
        W[tid] = make_float2(c, -s);
    }
    float2 d0;
    { float s, c; sincospif((float)ht * (1.0f / 4096.0f), &s, &c); d0 = make_float2(c, s); }

    float2* accs = half ? accsB : accsA;
#pragma unroll
    for (int k = 0; k < 16; ++k) accs[ht + 256 * k] = make_float2(0.0f, 0.0f);

    const int j = blockIdx.x >> 5;
    const int b = blockIdx.x & 31;
    __syncthreads();   // W visible

    // half h runs chains 4h..4h+3; chain c: i = c>>1, sp = c&1.
    // Buffer parity alternates per iteration within each half.
#pragma unroll 1
    for (int cc = 0; cc < 4; ++cc) {
        const int c  = half * 4 + cc;
        const int i  = c >> 1, sp = c & 1;
        const int r1 = (i * COUT + j) * RANK + 2 * sp;
        float2* A = hb[half][cc & 1];
        float2* B = hb[half][(cc & 1) ^ 1];
        do_chain(g_Hf[r1], g_Hf[r1 + 1], g_Gf[r1], g_Gf[r1 + 1],
                 g_Xf[i * BATCH + b], A, B, accs, W, d0, ht);
    }

    // Final IFFT (radix-8, all 512 threads) of accsA+accsB.
    // Buffers: half-0's pair. cc=3 (parity 1): A=hb[0][1], B=hb[0][0];
    // hb[0][0]'s last read was before bar5; stores below are post-bar6. Safe.
    __syncthreads();                                   // bar6: accs complete
    float2 v8[8];
#pragma unroll
    for (int k = 0; k < 8; ++k) {
        const int n = tid + 512 * k;
        v8[k] = cadd(accsA[n], accsB[n]);
    }
    stage_store8<1>(v8, hb[0][0], W, tid, 0);          // s = 1
    __syncthreads();
    stage_load8(v8, hb[0][0], tid);
    stage_store8<1>(v8, hb[0][1], W, tid, 3);          // s = 8
    __syncthreads();
    stage_load8(v8, hb[0][1], tid);
    stage_store8<1>(v8, hb[0][0], W, tid, 6);          // s = 64
    __syncthreads();
    stage_load8(v8, hb[0][0], tid);
    bf8<1>(v8);                                        // s = 512, k1 = 0
    float* op = out + (j * BATCH + b) * NN;
    const float inv = 1.0f / (2.0f * (float)NN);
#pragma unroll
    for (int k = 0; k < 8; ++k) op[tid + 512 * k] = v8[k].x * inv;
}

extern "C" void kernel_launch(void* const* d_in, const int* in_sizes, int n_in,
                              void* d_out, int out_size)
{
    const float* x = (const float*)d_in[0];   // (4, 32, 4096)
    const float* G = (const float*)d_in[1];   // (4, 4, 4, 4096)
    const float* H = (const float*)d_in[2];   // (4, 4, 4, 4096)
    float* out = (float*)d_out;               // (4, 32, 4096)

    cudaFuncSetAttribute(ldr_prep_kernel, cudaFuncAttributeMaxDynamicSharedMemorySize, PREP_SMEM);
    cudaFuncSetAttribute(ldr_main_kernel, cudaFuncAttributeMaxDynamicSharedMemorySize, MAIN_SMEM);

    ldr_prep_kernel<<<128, NTP, PREP_SMEM>>>(x, G, H);
    ldr_main_kernel<<<128, NTM, MAIN_SMEM>>>(out);
}

// round 14
// speedup vs baseline: 1.5659x; 1.5659x over previous
#include <cuda_runtime.h>

// LDR toeplitz-displacement layer via FFT with 2-term real packing everywhere.
//   Hf = fft(D*H); Gf = fft(G); Xf = ifft(conj(D)*x)
//   t = D*fft(Hf.Xf) is REAL => pack two chain terms: z = u1 + i*u2,
//   W = fft(D.fft(z)) = Tf1 + i*Tf2 (Tf Hermitian), unpack via reversed read.
//   out = Re(ifft(sum Gf.Tf)) / (2N).
// Prep (NT=256, 128 blk): packs PAIRS of real rows per FFT (sigma unpack).
// Main (NT=256, 128 blk): R10 structure + cp.async staging of next chain's
//   hf pair (every chain) and xf (every pair) into spare smem, issued after
//   bar1 (post-pack, post-barrier: no WAR race), waited before bar5 (>=2
//   barriers before consumption): hides the pack-phase L2 latency for free.
// FFT: radix-16 Stockham, 2 smem exchanges, in-place digit-swapped DFT16,
// hybrid twiddles (w1..w8 live, k>=8 via w8 * w_{k-8}).

#define NN    4096
#define CIN   4
#define COUT  4
#define RANK  4
#define BATCH 32

#define NT    256
#define PIDX16(i) ((i) + ((i) >> 4))
#define NPAD16 4352
#define W16SIZE 256
#define PREP_SMEM ((2 * NPAD16 + W16SIZE) * (int)sizeof(float2))
// main: b0 b1 + W[256] + staging sH1[NN] sH2[NN] sX[NN]
#define MAIN_SMEM ((2 * NPAD16 + W16SIZE + 3 * NN) * (int)sizeof(float2))

#define SW16(m) ((((m) & 3) << 2) | ((m) >> 2))

__device__ float2 g_Hf[CIN*COUT*RANK][NN];   // 2 MB
__device__ float2 g_Gf[CIN*COUT*RANK][NN];   // 2 MB
__device__ float2 g_Xf[CIN*BATCH][NN];       // 4 MB

__device__ __forceinline__ float2 cmul(float2 a, float2 b) {
    return make_float2(a.x*b.x - a.y*b.y, a.x*b.y + a.y*b.x);
}
__device__ __forceinline__ float2 cadd(float2 a, float2 b) { return make_float2(a.x+b.x, a.y+b.y); }
__device__ __forceinline__ float2 csub(float2 a, float2 b) { return make_float2(a.x-b.x, a.y-b.y); }

// ---- cp.async helpers ----
__device__ __forceinline__ void cp16(float2* smem_dst, const float2* gsrc) {
    unsigned saddr = (unsigned)__cvta_generic_to_shared(smem_dst);
    asm volatile("cp.async.cg.shared.global [%0], [%1], 16;\n" :: "r"(saddr), "l"(gsrc));
}
__device__ __forceinline__ void cp_commit() {
    asm volatile("cp.async.commit_group;\n" ::: "memory");
}
__device__ __forceinline__ void cp_wait_all() {
    asm volatile("cp.async.wait_group 0;\n" ::: "memory");
}
// copy one 4096-float2 row: 256 threads x 8 chunks of 16B
__device__ __forceinline__ void prefetch_row(float2* dst, const float2* src, int tid) {
#pragma unroll
    for (int i = 0; i < 8; ++i) {
        const int o = 2 * (tid + 256 * i);
        cp16(dst + o, src + o);
    }
}

// ============ radix-16 machinery (in-place digit-swapped DFT16) =============
// dft16A: natural in -> X[k] at slot SW16(k). dft16B: swapped in -> X[k] at k.

template<int INV>
__device__ __forceinline__ void dft4ip(float2& a, float2& b, float2& c, float2& d) {
    float2 t0 = cadd(a,c), t1 = csub(a,c), t2 = cadd(b,d), bd = csub(b,d);
    float2 t3 = INV ? make_float2(-bd.y, bd.x) : make_float2(bd.y, -bd.x);
    a = cadd(t0,t2); b = cadd(t1,t3); c = csub(t0,t2); d = csub(t1,t3);
}

template<int INV>
__device__ __forceinline__ void tw16ip(float2 v[16]) {
    const float C1 = 0.92387953251128675613f;
    const float S1 = 0.38268343236508977172f;
    const float CC = 0.70710678118654752440f;
#define TW(m, c, s) v[m] = cmul(v[m], make_float2((c), INV ? (s) : -(s)))
    TW(5,  C1,  S1);
    TW(6,  CC,  CC);
    TW(7,  S1,  C1);
    TW(9,  CC,  CC);
    TW(10, 0.0f, 1.0f);
    TW(11, -CC, CC);
    TW(13, S1,  C1);
    TW(14, -CC, CC);
    TW(15, -C1, -S1);
#undef TW
}

template<int INV>
__device__ __forceinline__ void dft16A(float2 v[16]) {
#pragma unroll
    for (int n0 = 0; n0 < 4; ++n0) dft4ip<INV>(v[n0], v[n0+4], v[n0+8], v[n0+12]);
    tw16ip<INV>(v);
#pragma unroll
    for (int q = 0; q < 4; ++q) dft4ip<INV>(v[4*q], v[4*q+1], v[4*q+2], v[4*q+3]);
}

template<int INV>
__device__ __forceinline__ void dft16B(float2 v[16]) {
#pragma unroll
    for (int q = 0; q < 4; ++q) dft4ip<INV>(v[4*q], v[4*q+1], v[4*q+2], v[4*q+3]);
    tw16ip<INV>(v);
#pragma unroll
    for (int n0 = 0; n0 < 4; ++n0) dft4ip<INV>(v[n0], v[n0+4], v[n0+8], v[n0+12]);
}

// butterfly + hybrid twiddle scatter: w1..w8 live; k>=8 -> (o*w8)*w_{k-8}.
template<int INV, int IN_SWAPPED>
__device__ __forceinline__ void stage_store16(float2 v[16], float2* __restrict__ sb,
                                              const float2* __restrict__ W,
                                              int u, int sshift) {
    if (IN_SWAPPED) dft16B<INV>(v); else dft16A<INV>(v);
    const int s  = 1 << sshift;
    const int k1 = u & ~(s - 1);
    const int base = u + 15 * k1;
    float2 w1 = W[k1];
    if (INV) w1.y = -w1.y;
    const float2 w2 = cmul(w1, w1);
    const float2 w3 = cmul(w2, w1);
    const float2 w4 = cmul(w2, w2);
    const float2 w5 = cmul(w4, w1);
    const float2 w6 = cmul(w4, w2);
    const float2 w7 = cmul(w4, w3);
    const float2 w8 = cmul(w4, w4);
    const float2 wlo[8] = { make_float2(1.0f, 0.0f), w1, w2, w3, w4, w5, w6, w7 };
#pragma unroll
    for (int k = 0; k < 16; ++k) {
        float2 o = IN_SWAPPED ? v[k] : v[SW16(k)];
        if (k >= 8) o = cmul(o, w8);
        if (k & 7)  o = cmul(o, wlo[k & 7]);
        sb[PIDX16(base + k * s)] = o;
    }
}

__device__ __forceinline__ void stage_load16(float2 v[16], const float2* __restrict__ sb, int tid) {
#pragma unroll
    for (int k = 0; k < 16; ++k) v[k] = sb[PIDX16(tid + 256 * k)];
}

// ================ K1: prep, 2 real rows packed per FFT ======================
// bid<32: Hf pair; 32<=bid<64: Gf pair; 64<=bid<128: Xf pair.

__global__ void __launch_bounds__(NT, 2) ldr_prep_kernel(const float* __restrict__ x,
                                                         const float* __restrict__ G,
                                                         const float* __restrict__ H)
{
    extern __shared__ float2 smem2[];
    float2* b0 = smem2;
    float2* b1 = smem2 + NPAD16;
    float2* W  = smem2 + 2 * NPAD16;
    const int tid = threadIdx.x;
    {
        float s, c; sincospif((float)tid * (1.0f / 2048.0f), &s, &c);
        W[tid] = make_float2(c, -s);
    }

    const int bid = blockIdx.x;
    float2 v[16];
    float2 *dst1, *dst2;
    int inv_mode = 0;
    int shift_rev = 1;       // sigma(n) = (shift_rev - n) mod N
    float scale = 0.5f;

    if (bid < 32) {          // Hf rows 2bid, 2bid+1: fft(D * h)
        const float* h1 = H + (2 * bid) * NN;
        const float* h2 = H + (2 * bid + 1) * NN;
#pragma unroll
        for (int k = 0; k < 16; ++k) {
            const int n = tid + 256 * k;
            float s, c; sincospif((float)n * (1.0f / 4096.0f), &s, &c);
            v[k] = cmul(make_float2(c, s), make_float2(h1[n], h2[n]));
        }
        dst1 = g_Hf[2 * bid]; dst2 = g_Hf[2 * bid + 1];
    } else if (bid < 64) {   // Gf rows: fft(g)
        const int r = bid - 32;
        const float* g1 = G + (2 * r) * NN;
        const float* g2 = G + (2 * r + 1) * NN;
#pragma unroll
        for (int k = 0; k < 16; ++k) {
            const int n = tid + 256 * k;
            v[k] = make_float2(g1[n], g2[n]);
        }
        dst1 = g_Gf[2 * r]; dst2 = g_Gf[2 * r + 1];
        shift_rev = 0;       // plain Hermitian
    } else {                 // Xf rows: ifft(conj(D) * x) with 1/N
        const int r = bid - 64;
        const float* x1 = x + (2 * r) * NN;
        const float* x2 = x + (2 * r + 1) * NN;
#pragma unroll
        for (int k = 0; k < 16; ++k) {
            const int n = tid + 256 * k;
            float s, c; sincospif((float)n * (1.0f / 4096.0f), &s, &c);
            v[k] = cmul(make_float2(c, -s), make_float2(x1[n], x2[n]));
        }
        dst1 = g_Xf[2 * r]; dst2 = g_Xf[2 * r + 1];
        inv_mode = 1;
        scale = 0.5f / (float)NN;
    }
    __syncthreads();   // W visible

    if (!inv_mode) {
        stage_store16<0,0>(v, b0, W, tid, 0);
        __syncthreads();
        stage_load16(v, b0, tid);
        stage_store16<0,0>(v, b1, W, tid, 4);
        __syncthreads();
        stage_load16(v, b1, tid);
        dft16A<0>(v);                      // swapped
    } else {
        stage_store16<1,0>(v, b0, W, tid, 0);
        __syncthreads();
        stage_load16(v, b0, tid);
        stage_store16<1,0>(v, b1, W, tid, 4);
        __syncthreads();
        stage_load16(v, b1, tid);
        dft16A<1>(v);                      // swapped
    }

    // unpack exchange through b0
#pragma unroll
    for (int k = 0; k < 16; ++k) b0[PIDX16(tid + 256 * k)] = v[SW16(k)];
    __syncthreads();
#pragma unroll
    for (int k = 0; k < 16; ++k) {
        const int n   = tid + 256 * k;
        const int sg  = (shift_rev - n) & (NN - 1);
        const float2 z  = v[SW16(k)];
        const float2 ws = b0[PIDX16(sg)];
        dst1[n] = make_float2(scale * (z.x + ws.x), scale * (z.y - ws.y));
        dst2[n] = make_float2(scale * (z.y + ws.y), scale * (ws.x - z.x));
    }
}

// ===================== K2: main (one (j,b) per block) =======================

// e^{i*pi*k/16}
__device__ __constant__ float E16C[16] = { 1.0f, 0.98078528040323044913f,
    0.92387953251128675613f, 0.83146961230254523708f, 0.70710678118654752440f,
    0.55557023301960222474f, 0.38268343236508977172f, 0.19509032201612826785f,
    0.0f, -0.19509032201612826785f, -0.38268343236508977172f,
    -0.55557023301960222474f, -0.70710678118654752440f, -0.83146961230254523708f,
    -0.92387953251128675613f, -0.98078528040323044913f };
__device__ __constant__ float E16S[16] = { 0.0f, 0.19509032201612826785f,
    0.38268343236508977172f, 0.55557023301960222474f, 0.70710678118654752440f,
    0.83146961230254523708f, 0.92387953251128675613f, 0.98078528040323044913f,
    1.0f, 0.98078528040323044913f, 0.92387953251128675613f,
    0.83146961230254523708f, 0.70710678118654752440f, 0.55557023301960222474f,
    0.38268343236508977172f, 0.19509032201612826785f };

__global__ void __launch_bounds__(NT, 1) ldr_main_kernel(float* __restrict__ out)
{
    extern __shared__ float2 smem2[];
    float2* b0  = smem2;
    float2* b1  = smem2 + NPAD16;
    float2* W   = smem2 + 2 * NPAD16;
    float2* sH1 = W + W16SIZE;            // staged hf1 of current chain (c>=1)
    float2* sH2 = sH1 + NN;               // staged hf2
    float2* sX  = sH2 + NN;               // staged xf of current pair (c>=2)
    const int tid = threadIdx.x;
    {
        float s, c; sincospif((float)tid * (1.0f / 2048.0f), &s, &c);
        W[tid] = make_float2(c, -s);
    }
    float2 d0;
    { float s, c; sincospif((float)tid * (1.0f / 4096.0f), &s, &c); d0 = make_float2(c, s); }
    __syncthreads();   // W visible

    const int j = blockIdx.x >> 5;
    const int b = blockIdx.x & 31;

    float2 acc[16];
#pragma unroll
    for (int k = 0; k < 16; ++k) acc[k] = make_float2(0.0f, 0.0f);

    // 8 chains: chain c -> i = c>>1, sp = c&1, rows r1, r1+1. Pairs (2p,2p+1)
    // share xf. Buffer parity alternates per chain: even A=b0, odd A=b1.
#pragma unroll 1
    for (int c = 0; c < 8; ++c) {
        const int i  = c >> 1, sp = c & 1;
        const int r1 = (i * COUT + j) * RANK + 2 * sp;
        const float2* __restrict__ gf1 = g_Gf[r1];
        const float2* __restrict__ gf2 = g_Gf[r1 + 1];
        // pack inputs: staged when available
        const float2* __restrict__ hf1 = (c == 0) ? g_Hf[r1]     : sH1;
        const float2* __restrict__ hf2 = (c == 0) ? g_Hf[r1 + 1] : sH2;
        const float2* __restrict__ xf  = (c < 2)  ? g_Xf[i * BATCH + b] : sX;
        float2* A = (c & 1) ? b1 : b0;
        float2* B = (c & 1) ? b0 : b1;

        float2 v[16];
#pragma unroll
        for (int k = 0; k < 16; ++k) {
            const int n = tid + 256 * k;
            const float2 xv = xf[n];
            const float2 u1 = cmul(hf1[n], xv);
            const float2 u2 = cmul(hf2[n], xv);
            v[k] = make_float2(u1.x - u2.y, u1.y + u2.x);   // u1 + i*u2
        }
        // fft #1
        stage_store16<0,0>(v, A, W, tid, 0);
        __syncthreads();                                   // bar1
        // issue prefetches for the NEXT chain (post-barrier: pack reads done)
        if (c < 7) {
            const int cn  = c + 1;
            const int rn  = ((cn >> 1) * COUT + j) * RANK + 2 * (cn & 1);
            prefetch_row(sH1, g_Hf[rn],     tid);
            prefetch_row(sH2, g_Hf[rn + 1], tid);
            if (c & 1) prefetch_row(sX, g_Xf[((cn >> 1)) * BATCH + b], tid);
            cp_commit();
        }
        stage_load16(v, A, tid);
        stage_store16<0,0>(v, B, W, tid, 4);
        __syncthreads();                                   // bar2
        stage_load16(v, B, tid);
        dft16A<0>(v);                                      // swapped
        // D multiply in swapped slots: slot m holds n = tid + 256*SW16(m)
#pragma unroll
        for (int m = 0; m < 16; ++m)
            v[m] = cmul(v[m], cmul(d0, make_float2(E16C[SW16(m)], E16S[SW16(m)])));
        // fft #2 (input swapped)
        stage_store16<0,1>(v, A, W, tid, 0);
        __syncthreads();                                   // bar3
        stage_load16(v, A, tid);
        stage_store16<0,0>(v, B, W, tid, 4);
        __syncthreads();                                   // bar4
        stage_load16(v, B, tid);
        dft16A<0>(v);                                      // swapped
        // Hermitian unpack through A
#pragma unroll
        for (int k = 0; k < 16; ++k) A[PIDX16(tid + 256 * k)] = v[SW16(k)];
        if (c < 7) cp_wait_all();   // staging done before bar5 -> visible after
        __syncthreads();                                   // bar5
#pragma unroll
        for (int k = 0; k < 16; ++k) {
            const int n   = tid + 256 * k;
            const int rev = (NN - n) & (NN - 1);
            const float2 ws = A[PIDX16(rev)];
            const float2 vk = v[SW16(k)];
            const float2 t1 = make_float2(vk.x + ws.x, vk.y - ws.y);   // 2*Tf1
            const float2 t2 = make_float2(vk.y + ws.y, ws.x - vk.x);   // 2*Tf2
            acc[k] = cadd(acc[k], cadd(cmul(gf1[n], t1), cmul(gf2[n], t2)));
        }
    }

    // final IFFT of acc. Chain 7 (A=b1): b0's last reads pre-unpack-barrier,
    // so storing b0 first is one-barrier separated.
    stage_store16<1,0>(acc, b0, W, tid, 0);
    __syncthreads();
    stage_load16(acc, b0, tid);
    stage_store16<1,0>(acc, b1, W, tid, 4);
    __syncthreads();
    stage_load16(acc, b1, tid);
    dft16A<1>(acc);                                    // swapped
    float* op = out + (j * BATCH + b) * NN;
    const float inv = 1.0f / (2.0f * (float)NN);
#pragma unroll
    for (int k = 0; k < 16; ++k) op[tid + 256 * k] = acc[SW16(k)].x * inv;
}

extern "C" void kernel_launch(void* const* d_in, const int* in_sizes, int n_in,
                              void* d_out, int out_size)
{
    const float* x = (const float*)d_in[0];   // (4, 32, 4096)
    const float* G = (const float*)d_in[1];   // (4, 4, 4, 4096)
    const float* H = (const float*)d_in[2];   // (4, 4, 4, 4096)
    float* out = (float*)d_out;               // (4, 32, 4096)

    cudaFuncSetAttribute(ldr_prep_kernel, cudaFuncAttributeMaxDynamicSharedMemorySize, PREP_SMEM);
    cudaFuncSetAttribute(ldr_main_kernel, cudaFuncAttributeMaxDynamicSharedMemorySize, MAIN_SMEM);

    ldr_prep_kernel<<<128, NT, PREP_SMEM>>>(x, G, H);
    ldr_main_kernel<<<128, NT, MAIN_SMEM>>>(out);
}

// round 15
// speedup vs baseline: 1.6432x; 1.0494x over previous
#include <cuda_runtime.h>

// LDR toeplitz-displacement layer via FFT with 2-term real packing everywhere.
//   Hf = fft(D*H); Gf = fft(G); Xf = ifft(conj(D)*x)
//   t = D*fft(Hf.Xf) is REAL => pack two chain terms: z = u1 + i*u2,
//   W = fft(D.fft(z)) = Tf1 + i*Tf2 (Tf Hermitian), unpack via reversed read.
//   out = Re(ifft(sum Gf.Tf)) / (2N).
// Prep (NT=256, 128 blk): packs PAIRS of real rows per FFT (sigma unpack).
// Main (NT=256, 128 blk): R14 + gf staging. cp.async stages, per chain c:
//   - gf1(c), gf2(c)   (consumed in accumulate after bar5 of chain c)
//   - hf pair of c+1   (consumed at next chain's pack)
//   issued after bar1 (post-pack, post-barrier: no WAR), waited before bar5.
//   xf read direct from L2. NO W table: Stockham twiddle bases are per-thread
//   constants (k1 = tid for s=1, tid&~15 for s=16) -> two registers, no LDS.
// FFT: radix-16 Stockham, 2 smem exchanges, in-place digit-swapped DFT16,
// hybrid twiddles (w1..w8 live, k>=8 via w8 * w_{k-8}).

#define NN    4096
#define CIN   4
#define COUT  4
#define RANK  4
#define BATCH 32

#define NT    256
#define PIDX16(i) ((i) + ((i) >> 4))
#define NPAD16 4352
#define W16SIZE 256
#define PREP_SMEM ((2 * NPAD16 + W16SIZE) * (int)sizeof(float2))
// main: b0 b1 + staging sH1[NN] sH2[NN] sG1[NN] sG2[NN]   (no W table)
#define MAIN_SMEM ((2 * NPAD16 + 4 * NN) * (int)sizeof(float2))

#define SW16(m) ((((m) & 3) << 2) | ((m) >> 2))

__device__ float2 g_Hf[CIN*COUT*RANK][NN];   // 2 MB
__device__ float2 g_Gf[CIN*COUT*RANK][NN];   // 2 MB
__device__ float2 g_Xf[CIN*BATCH][NN];       // 4 MB

__device__ __forceinline__ float2 cmul(float2 a, float2 b) {
    return make_float2(a.x*b.x - a.y*b.y, a.x*b.y + a.y*b.x);
}
__device__ __forceinline__ float2 cadd(float2 a, float2 b) { return make_float2(a.x+b.x, a.y+b.y); }
__device__ __forceinline__ float2 csub(float2 a, float2 b) { return make_float2(a.x-b.x, a.y-b.y); }

// ---- cp.async helpers ----
__device__ __forceinline__ void cp16(float2* smem_dst, const float2* gsrc) {
    unsigned saddr = (unsigned)__cvta_generic_to_shared(smem_dst);
    asm volatile("cp.async.cg.shared.global [%0], [%1], 16;\n" :: "r"(saddr), "l"(gsrc));
}
__device__ __forceinline__ void cp_commit() {
    asm volatile("cp.async.commit_group;\n" ::: "memory");
}
__device__ __forceinline__ void cp_wait_all() {
    asm volatile("cp.async.wait_group 0;\n" ::: "memory");
}
// copy one 4096-float2 row: 256 threads x 8 chunks of 16B
__device__ __forceinline__ void prefetch_row(float2* dst, const float2* src, int tid) {
#pragma unroll
    for (int i = 0; i < 8; ++i) {
        const int o = 2 * (tid + 256 * i);
        cp16(dst + o, src + o);
    }
}

// ============ radix-16 machinery (in-place digit-swapped DFT16) =============
// dft16A: natural in -> X[k] at slot SW16(k). dft16B: swapped in -> X[k] at k.

template<int INV>
__device__ __forceinline__ void dft4ip(float2& a, float2& b, float2& c, float2& d) {
    float2 t0 = cadd(a,c), t1 = csub(a,c), t2 = cadd(b,d), bd = csub(b,d);
    float2 t3 = INV ? make_float2(-bd.y, bd.x) : make_float2(bd.y, -bd.x);
    a = cadd(t0,t2); b = cadd(t1,t3); c = csub(t0,t2); d = csub(t1,t3);
}

template<int INV>
__device__ __forceinline__ void tw16ip(float2 v[16]) {
    const float C1 = 0.92387953251128675613f;
    const float S1 = 0.38268343236508977172f;
    const float CC = 0.70710678118654752440f;
#define TW(m, c, s) v[m] = cmul(v[m], make_float2((c), INV ? (s) : -(s)))
    TW(5,  C1,  S1);
    TW(6,  CC,  CC);
    TW(7,  S1,  C1);
    TW(9,  CC,  CC);
    TW(10, 0.0f, 1.0f);
    TW(11, -CC, CC);
    TW(13, S1,  C1);
    TW(14, -CC, CC);
    TW(15, -C1, -S1);
#undef TW
}

template<int INV>
__device__ __forceinline__ void dft16A(float2 v[16]) {
#pragma unroll
    for (int n0 = 0; n0 < 4; ++n0) dft4ip<INV>(v[n0], v[n0+4], v[n0+8], v[n0+12]);
    tw16ip<INV>(v);
#pragma unroll
    for (int q = 0; q < 4; ++q) dft4ip<INV>(v[4*q], v[4*q+1], v[4*q+2], v[4*q+3]);
}

template<int INV>
__device__ __forceinline__ void dft16B(float2 v[16]) {
#pragma unroll
    for (int q = 0; q < 4; ++q) dft4ip<INV>(v[4*q], v[4*q+1], v[4*q+2], v[4*q+3]);
    tw16ip<INV>(v);
#pragma unroll
    for (int n0 = 0; n0 < 4; ++n0) dft4ip<INV>(v[n0], v[n0+4], v[n0+8], v[n0+12]);
}

// butterfly + hybrid twiddle scatter. w1raw = W4096^{k1} (forward value;
// conjugated here if INV). w1..w8 live; k>=8 -> (o*w8)*w_{k-8}.
template<int INV, int IN_SWAPPED>
__device__ __forceinline__ void stage_store16(float2 v[16], float2* __restrict__ sb,
                                              float2 w1raw, int u, int sshift) {
    if (IN_SWAPPED) dft16B<INV>(v); else dft16A<INV>(v);
    const int s  = 1 << sshift;
    const int k1 = u & ~(s - 1);
    const int base = u + 15 * k1;
    float2 w1 = w1raw;
    if (INV) w1.y = -w1.y;
    const float2 w2 = cmul(w1, w1);
    const float2 w3 = cmul(w2, w1);
    const float2 w4 = cmul(w2, w2);
    const float2 w5 = cmul(w4, w1);
    const float2 w6 = cmul(w4, w2);
    const float2 w7 = cmul(w4, w3);
    const float2 w8 = cmul(w4, w4);
    const float2 wlo[8] = { make_float2(1.0f, 0.0f), w1, w2, w3, w4, w5, w6, w7 };
#pragma unroll
    for (int k = 0; k < 16; ++k) {
        float2 o = IN_SWAPPED ? v[k] : v[SW16(k)];
        if (k >= 8) o = cmul(o, w8);
        if (k & 7)  o = cmul(o, wlo[k & 7]);
        sb[PIDX16(base + k * s)] = o;
    }
}

__device__ __forceinline__ void stage_load16(float2 v[16], const float2* __restrict__ sb, int tid) {
#pragma unroll
    for (int k = 0; k < 16; ++k) v[k] = sb[PIDX16(tid + 256 * k)];
}

// ================ K1: prep, 2 real rows packed per FFT ======================
// bid<32: Hf pair; 32<=bid<64: Gf pair; 64<=bid<128: Xf pair.
// (Uses the same per-thread twiddle registers; no smem W table.)

__global__ void __launch_bounds__(NT, 2) ldr_prep_kernel(const float* __restrict__ x,
                                                         const float* __restrict__ G,
                                                         const float* __restrict__ H)
{
    extern __shared__ float2 smem2[];
    float2* b0 = smem2;
    float2* b1 = smem2 + NPAD16;
    const int tid = threadIdx.x;
    float2 wA, wB;
    { float s, c; sincospif((float)tid * (1.0f / 2048.0f), &s, &c);         wA = make_float2(c, -s); }
    { float s, c; sincospif((float)(tid & ~15) * (1.0f / 2048.0f), &s, &c); wB = make_float2(c, -s); }

    const int bid = blockIdx.x;
    float2 v[16];
    float2 *dst1, *dst2;
    int inv_mode = 0;
    int shift_rev = 1;       // sigma(n) = (shift_rev - n) mod N
    float scale = 0.5f;

    if (bid < 32) {          // Hf rows 2bid, 2bid+1: fft(D * h)
        const float* h1 = H + (2 * bid) * NN;
        const float* h2 = H + (2 * bid + 1) * NN;
#pragma unroll
        for (int k = 0; k < 16; ++k) {
            const int n = tid + 256 * k;
            float s, c; sincospif((float)n * (1.0f / 4096.0f), &s, &c);
            v[k] = cmul(make_float2(c, s), make_float2(h1[n], h2[n]));
        }
        dst1 = g_Hf[2 * bid]; dst2 = g_Hf[2 * bid + 1];
    } else if (bid < 64) {   // Gf rows: fft(g)
        const int r = bid - 32;
        const float* g1 = G + (2 * r) * NN;
        const float* g2 = G + (2 * r + 1) * NN;
#pragma unroll
        for (int k = 0; k < 16; ++k) {
            const int n = tid + 256 * k;
            v[k] = make_float2(g1[n], g2[n]);
        }
        dst1 = g_Gf[2 * r]; dst2 = g_Gf[2 * r + 1];
        shift_rev = 0;       // plain Hermitian
    } else {                 // Xf rows: ifft(conj(D) * x) with 1/N
        const int r = bid - 64;
        const float* x1 = x + (2 * r) * NN;
        const float* x2 = x + (2 * r + 1) * NN;
#pragma unroll
        for (int k = 0; k < 16; ++k) {
            const int n = tid + 256 * k;
            float s, c; sincospif((float)n * (1.0f / 4096.0f), &s, &c);
            v[k] = cmul(make_float2(c, -s), make_float2(x1[n], x2[n]));
        }
        dst1 = g_Xf[2 * r]; dst2 = g_Xf[2 * r + 1];
        inv_mode = 1;
        scale = 0.5f / (float)NN;
    }

    if (!inv_mode) {
        stage_store16<0,0>(v, b0, wA, tid, 0);
        __syncthreads();
        stage_load16(v, b0, tid);
        stage_store16<0,0>(v, b1, wB, tid, 4);
        __syncthreads();
        stage_load16(v, b1, tid);
        dft16A<0>(v);                      // swapped
    } else {
        stage_store16<1,0>(v, b0, wA, tid, 0);
        __syncthreads();
        stage_load16(v, b0, tid);
        stage_store16<1,0>(v, b1, wB, tid, 4);
        __syncthreads();
        stage_load16(v, b1, tid);
        dft16A<1>(v);                      // swapped
    }

    // unpack exchange through b0
#pragma unroll
    for (int k = 0; k < 16; ++k) b0[PIDX16(tid + 256 * k)] = v[SW16(k)];
    __syncthreads();
#pragma unroll
    for (int k = 0; k < 16; ++k) {
        const int n   = tid + 256 * k;
        const int sg  = (shift_rev - n) & (NN - 1);
        const float2 z  = v[SW16(k)];
        const float2 ws = b0[PIDX16(sg)];
        dst1[n] = make_float2(scale * (z.x + ws.x), scale * (z.y - ws.y));
        dst2[n] = make_float2(scale * (z.y + ws.y), scale * (ws.x - z.x));
    }
}

// ===================== K2: main (one (j,b) per block) =======================

// e^{i*pi*k/16}
__device__ __constant__ float E16C[16] = { 1.0f, 0.98078528040323044913f,
    0.92387953251128675613f, 0.83146961230254523708f, 0.70710678118654752440f,
    0.55557023301960222474f, 0.38268343236508977172f, 0.19509032201612826785f,
    0.0f, -0.19509032201612826785f, -0.38268343236508977172f,
    -0.55557023301960222474f, -0.70710678118654752440f, -0.83146961230254523708f,
    -0.92387953251128675613f, -0.98078528040323044913f };
__device__ __constant__ float E16S[16] = { 0.0f, 0.19509032201612826785f,
    0.38268343236508977172f, 0.55557023301960222474f, 0.70710678118654752440f,
    0.83146961230254523708f, 0.92387953251128675613f, 0.98078528040323044913f,
    1.0f, 0.98078528040323044913f, 0.92387953251128675613f,
    0.83146961230254523708f, 0.70710678118654752440f, 0.55557023301960222474f,
    0.38268343236508977172f, 0.19509032201612826785f };

__global__ void __launch_bounds__(NT, 1) ldr_main_kernel(float* __restrict__ out)
{
    extern __shared__ float2 smem2[];
    float2* b0  = smem2;
    float2* b1  = smem2 + NPAD16;
    float2* sH1 = smem2 + 2 * NPAD16;     // staged hf1 of current chain (c>=1)
    float2* sH2 = sH1 + NN;               // staged hf2
    float2* sG1 = sH2 + NN;               // staged gf1 of current chain
    float2* sG2 = sG1 + NN;               // staged gf2
    const int tid = threadIdx.x;
    float2 wA, wB, d0;
    { float s, c; sincospif((float)tid * (1.0f / 2048.0f), &s, &c);         wA = make_float2(c, -s); }
    { float s, c; sincospif((float)(tid & ~15) * (1.0f / 2048.0f), &s, &c); wB = make_float2(c, -s); }
    { float s, c; sincospif((float)tid * (1.0f / 4096.0f), &s, &c);         d0 = make_float2(c,  s); }

    const int j = blockIdx.x >> 5;
    const int b = blockIdx.x & 31;

    float2 acc[16];
#pragma unroll
    for (int k = 0; k < 16; ++k) acc[k] = make_float2(0.0f, 0.0f);

    // 8 chains: chain c -> i = c>>1, sp = c&1, rows r1, r1+1. Pairs (2p,2p+1)
    // share xf. Buffer parity alternates per chain: even A=b0, odd A=b1.
#pragma unroll 1
    for (int c = 0; c < 8; ++c) {
        const int i  = c >> 1, sp = c & 1;
        const int r1 = (i * COUT + j) * RANK + 2 * sp;
        // pack inputs: hf staged for c>=1; xf direct (L2)
        const float2* __restrict__ hf1 = (c == 0) ? g_Hf[r1]     : sH1;
        const float2* __restrict__ hf2 = (c == 0) ? g_Hf[r1 + 1] : sH2;
        const float2* __restrict__ xf  = g_Xf[i * BATCH + b];
        float2* A = (c & 1) ? b1 : b0;
        float2* B = (c & 1) ? b0 : b1;

        float2 v[16];
#pragma unroll
        for (int k = 0; k < 16; ++k) {
            const int n = tid + 256 * k;
            const float2 xv = xf[n];
            const float2 u1 = cmul(hf1[n], xv);
            const float2 u2 = cmul(hf2[n], xv);
            v[k] = make_float2(u1.x - u2.y, u1.y + u2.x);   // u1 + i*u2
        }
        // fft #1
        stage_store16<0,0>(v, A, wA, tid, 0);
        __syncthreads();                                   // bar1
        // issue prefetches (post-barrier: pack reads + prior accumulate done):
        //   gf pair of THIS chain (consumed after bar5), hf pair of NEXT chain
        {
            prefetch_row(sG1, g_Gf[r1],     tid);
            prefetch_row(sG2, g_Gf[r1 + 1], tid);
            if (c < 7) {
                const int cn = c + 1;
                const int rn = ((cn >> 1) * COUT + j) * RANK + 2 * (cn & 1);
                prefetch_row(sH1, g_Hf[rn],     tid);
                prefetch_row(sH2, g_Hf[rn + 1], tid);
            }
            cp_commit();
        }
        stage_load16(v, A, tid);
        stage_store16<0,0>(v, B, wB, tid, 4);
        __syncthreads();                                   // bar2
        stage_load16(v, B, tid);
        dft16A<0>(v);                                      // swapped
        // D multiply in swapped slots: slot m holds n = tid + 256*SW16(m)
#pragma unroll
        for (int m = 0; m < 16; ++m)
            v[m] = cmul(v[m], cmul(d0, make_float2(E16C[SW16(m)], E16S[SW16(m)])));
        // fft #2 (input swapped)
        stage_store16<0,1>(v, A, wA, tid, 0);
        __syncthreads();                                   // bar3
        stage_load16(v, A, tid);
        stage_store16<0,0>(v, B, wB, tid, 4);
        __syncthreads();                                   // bar4
        stage_load16(v, B, tid);
        dft16A<0>(v);                                      // swapped
        // Hermitian unpack through A
#pragma unroll
        for (int k = 0; k < 16; ++k) A[PIDX16(tid + 256 * k)] = v[SW16(k)];
        cp_wait_all();            // staging done before bar5 -> visible after
        __syncthreads();                                   // bar5
#pragma unroll
        for (int k = 0; k < 16; ++k) {
            const int n   = tid + 256 * k;
            const int rev = (NN - n) & (NN - 1);
            const float2 ws = A[PIDX16(rev)];
            const float2 vk = v[SW16(k)];
            const float2 t1 = make_float2(vk.x + ws.x, vk.y - ws.y);   // 2*Tf1
            const float2 t2 = make_float2(vk.y + ws.y, ws.x - vk.x);   // 2*Tf2
            acc[k] = cadd(acc[k], cadd(cmul(sG1[n], t1), cmul(sG2[n], t2)));
        }
    }

    // final IFFT of acc. Chain 7 (A=b1): b0's last reads pre-unpack-barrier,
    // so storing b0 first is one-barrier separated.
    stage_store16<1,0>(acc, b0, wA, tid, 0);
    __syncthreads();
    stage_load16(acc, b0, tid);
    stage_store16<1,0>(acc, b1, wB, tid, 4);
    __syncthreads();
    stage_load16(acc, b1, tid);
    dft16A<1>(acc);                                    // swapped
    float* op = out + (j * BATCH + b) * NN;
    const float inv = 1.0f / (2.0f * (float)NN);
#pragma unroll
    for (int k = 0; k < 16; ++k) op[tid + 256 * k] = acc[SW16(k)].x * inv;
}

extern "C" void kernel_launch(void* const* d_in, const int* in_sizes, int n_in,
                              void* d_out, int out_size)
{
    const float* x = (const float*)d_in[0];   // (4, 32, 4096)
    const float* G = (const float*)d_in[1];   // (4, 4, 4, 4096)
    const float* H = (const float*)d_in[2];   // (4, 4, 4, 4096)
    float* out = (float*)d_out;               // (4, 32, 4096)

    cudaFuncSetAttribute(ldr_prep_kernel, cudaFuncAttributeMaxDynamicSharedMemorySize, PREP_SMEM);
    cudaFuncSetAttribute(ldr_main_kernel, cudaFuncAttributeMaxDynamicSharedMemorySize, MAIN_SMEM);

    ldr_prep_kernel<<<128, NT, PREP_SMEM>>>(x, G, H);
    ldr_main_kernel<<<128, NT, MAIN_SMEM>>>(out);
}

// round 16
// speedup vs baseline: 1.8111x; 1.1021x over previous
#include <cuda_runtime.h>

// LDR toeplitz-displacement layer via FFT, fully packed form.
//   Hz = fft(D*(h1+i*h2))  (= Hf1 + i*Hf2, raw)    [32 rows]
//   Gz = fft(g1+i*g2)      (= Gf1 + i*Gf2, raw)    [32 rows]
//   Xf = ifft(conj(D)*x)   (real-unpacked, true)   [128 rows]
// Chain (pair of terms): z = Hz.Xf ; Wv = fft(D.fft(z)) ;
//   acc[n] += Wv[n]*conj(Gz[rev n]) + conj(Wv[rev n])*Gz[n]   (rev = (N-n)%N)
//   out = Re(ifft(acc)) / (2N).
// Main: radix-16 Stockham (2 smem exchanges), in-place digit-swapped DFT16,
// register twiddles (w1..w8 hybrid) from 2 per-thread bases (no W table),
// cp.async staging of sG (this chain), sH (next chain), sX (next pair),
// issued after bar1 / waited before bar5 (WAR + visibility audited).

#define NN    4096
#define CIN   4
#define COUT  4
#define RANK  4
#define BATCH 32

#define NT    256
#define PIDX16(i) ((i) + ((i) >> 4))
#define NPAD16 4352
#define PREP_SMEM ((2 * NPAD16) * (int)sizeof(float2))
// main: b0 b1 + staging sH[NN] sG[NN] sX[NN]
#define MAIN_SMEM ((2 * NPAD16 + 3 * NN) * (int)sizeof(float2))

#define SW16(m) ((((m) & 3) << 2) | ((m) >> 2))

__device__ float2 g_Hz[CIN*COUT*RANK/2][NN];   // 1 MB
__device__ float2 g_Gz[CIN*COUT*RANK/2][NN];   // 1 MB
__device__ float2 g_Xf[CIN*BATCH][NN];         // 4 MB

__device__ __forceinline__ float2 cmul(float2 a, float2 b) {
    return make_float2(a.x*b.x - a.y*b.y, a.x*b.y + a.y*b.x);
}
__device__ __forceinline__ float2 cadd(float2 a, float2 b) { return make_float2(a.x+b.x, a.y+b.y); }
__device__ __forceinline__ float2 csub(float2 a, float2 b) { return make_float2(a.x-b.x, a.y-b.y); }
// a * conj(b)
__device__ __forceinline__ float2 cmulcj(float2 a, float2 b) {
    return make_float2(a.x*b.x + a.y*b.y, a.y*b.x - a.x*b.y);
}

// ---- cp.async helpers ----
__device__ __forceinline__ void cp16(float2* smem_dst, const float2* gsrc) {
    unsigned saddr = (unsigned)__cvta_generic_to_shared(smem_dst);
    asm volatile("cp.async.cg.shared.global [%0], [%1], 16;\n" :: "r"(saddr), "l"(gsrc));
}
__device__ __forceinline__ void cp_commit() {
    asm volatile("cp.async.commit_group;\n" ::: "memory");
}
__device__ __forceinline__ void cp_wait_all() {
    asm volatile("cp.async.wait_group 0;\n" ::: "memory");
}
__device__ __forceinline__ void prefetch_row(float2* dst, const float2* src, int tid) {
#pragma unroll
    for (int i = 0; i < 8; ++i) {
        const int o = 2 * (tid + 256 * i);
        cp16(dst + o, src + o);
    }
}

// ============ radix-16 machinery (in-place digit-swapped DFT16) =============

template<int INV>
__device__ __forceinline__ void dft4ip(float2& a, float2& b, float2& c, float2& d) {
    float2 t0 = cadd(a,c), t1 = csub(a,c), t2 = cadd(b,d), bd = csub(b,d);
    float2 t3 = INV ? make_float2(-bd.y, bd.x) : make_float2(bd.y, -bd.x);
    a = cadd(t0,t2); b = cadd(t1,t3); c = csub(t0,t2); d = csub(t1,t3);
}

template<int INV>
__device__ __forceinline__ void tw16ip(float2 v[16]) {
    const float C1 = 0.92387953251128675613f;
    const float S1 = 0.38268343236508977172f;
    const float CC = 0.70710678118654752440f;
#define TW(m, c, s) v[m] = cmul(v[m], make_float2((c), INV ? (s) : -(s)))
    TW(5,  C1,  S1);
    TW(6,  CC,  CC);
    TW(7,  S1,  C1);
    TW(9,  CC,  CC);
    TW(10, 0.0f, 1.0f);
    TW(11, -CC, CC);
    TW(13, S1,  C1);
    TW(14, -CC, CC);
    TW(15, -C1, -S1);
#undef TW
}

template<int INV>
__device__ __forceinline__ void dft16A(float2 v[16]) {
#pragma unroll
    for (int n0 = 0; n0 < 4; ++n0) dft4ip<INV>(v[n0], v[n0+4], v[n0+8], v[n0+12]);
    tw16ip<INV>(v);
#pragma unroll
    for (int q = 0; q < 4; ++q) dft4ip<INV>(v[4*q], v[4*q+1], v[4*q+2], v[4*q+3]);
}

template<int INV>
__device__ __forceinline__ void dft16B(float2 v[16]) {
#pragma unroll
    for (int q = 0; q < 4; ++q) dft4ip<INV>(v[4*q], v[4*q+1], v[4*q+2], v[4*q+3]);
    tw16ip<INV>(v);
#pragma unroll
    for (int n0 = 0; n0 < 4; ++n0) dft4ip<INV>(v[n0], v[n0+4], v[n0+8], v[n0+12]);
}

// butterfly + hybrid twiddle scatter. w1raw = W4096^{k1} (forward; conj if INV)
template<int INV, int IN_SWAPPED>
__device__ __forceinline__ void stage_store16(float2 v[16], float2* __restrict__ sb,
                                              float2 w1raw, int u, int sshift) {
    if (IN_SWAPPED) dft16B<INV>(v); else dft16A<INV>(v);
    const int s  = 1 << sshift;
    const int k1 = u & ~(s - 1);
    const int base = u + 15 * k1;
    float2 w1 = w1raw;
    if (INV) w1.y = -w1.y;
    const float2 w2 = cmul(w1, w1);
    const float2 w3 = cmul(w2, w1);
    const float2 w4 = cmul(w2, w2);
    const float2 w5 = cmul(w4, w1);
    const float2 w6 = cmul(w4, w2);
    const float2 w7 = cmul(w4, w3);
    const float2 w8 = cmul(w4, w4);
    const float2 wlo[8] = { make_float2(1.0f, 0.0f), w1, w2, w3, w4, w5, w6, w7 };
#pragma unroll
    for (int k = 0; k < 16; ++k) {
        float2 o = IN_SWAPPED ? v[k] : v[SW16(k)];
        if (k >= 8) o = cmul(o, w8);
        if (k & 7)  o = cmul(o, wlo[k & 7]);
        sb[PIDX16(base + k * s)] = o;
    }
}

__device__ __forceinline__ void stage_load16(float2 v[16], const float2* __restrict__ sb, int tid) {
#pragma unroll
    for (int k = 0; k < 16; ++k) v[k] = sb[PIDX16(tid + 256 * k)];
}

// ================ K1: prep =================================================
// bid<32: Hz[bid] = fft(D*(h1+i*h2)) raw (no unpack).
// 32<=bid<64: Gz = fft(g1+i*g2) raw (no unpack).
// 64<=bid<128: Xf pair = ifft(conj(D)*x) with real unpack + 1/N.

__global__ void __launch_bounds__(NT, 2) ldr_prep_kernel(const float* __restrict__ x,
                                                         const float* __restrict__ G,
                                                         const float* __restrict__ H)
{
    extern __shared__ float2 smem2[];
    float2* b0 = smem2;
    float2* b1 = smem2 + NPAD16;
    const int tid = threadIdx.x;
    float2 wA, wB;
    { float s, c; sincospif((float)tid * (1.0f / 2048.0f), &s, &c);         wA = make_float2(c, -s); }
    { float s, c; sincospif((float)(tid & ~15) * (1.0f / 2048.0f), &s, &c); wB = make_float2(c, -s); }

    const int bid = blockIdx.x;
    float2 v[16];

    if (bid < 64) {
        // packed forward FFT, stored raw
        float2* dst;
        if (bid < 32) {      // Hz: D * (h1 + i h2)
            const float* h1 = H + (2 * bid) * NN;
            const float* h2 = H + (2 * bid + 1) * NN;
#pragma unroll
            for (int k = 0; k < 16; ++k) {
                const int n = tid + 256 * k;
                float s, c; sincospif((float)n * (1.0f / 4096.0f), &s, &c);
                v[k] = cmul(make_float2(c, s), make_float2(h1[n], h2[n]));
            }
            dst = g_Hz[bid];
        } else {             // Gz: g1 + i g2
            const int r = bid - 32;
            const float* g1 = G + (2 * r) * NN;
            const float* g2 = G + (2 * r + 1) * NN;
#pragma unroll
            for (int k = 0; k < 16; ++k) {
                const int n = tid + 256 * k;
                v[k] = make_float2(g1[n], g2[n]);
            }
            dst = g_Gz[r];
        }
        stage_store16<0,0>(v, b0, wA, tid, 0);
        __syncthreads();
        stage_load16(v, b0, tid);
        stage_store16<0,0>(v, b1, wB, tid, 4);
        __syncthreads();
        stage_load16(v, b1, tid);
        dft16A<0>(v);                      // swapped
#pragma unroll
        for (int k = 0; k < 16; ++k) dst[tid + 256 * k] = v[SW16(k)];
    } else {
        // Xf pair: inverse + shifted-Hermitian unpack, scale 0.5/N
        const int r = bid - 64;
        const float* x1 = x + (2 * r) * NN;
        const float* x2 = x + (2 * r + 1) * NN;
#pragma unroll
        for (int k = 0; k < 16; ++k) {
            const int n = tid + 256 * k;
            float s, c; sincospif((float)n * (1.0f / 4096.0f), &s, &c);
            v[k] = cmul(make_float2(c, -s), make_float2(x1[n], x2[n]));
        }
        stage_store16<1,0>(v, b0, wA, tid, 0);
        __syncthreads();
        stage_load16(v, b0, tid);
        stage_store16<1,0>(v, b1, wB, tid, 4);
        __syncthreads();
        stage_load16(v, b1, tid);
        dft16A<1>(v);                      // swapped
        // unpack exchange through b0 (its last readers are pre-barrier)
#pragma unroll
        for (int k = 0; k < 16; ++k) b0[PIDX16(tid + 256 * k)] = v[SW16(k)];
        __syncthreads();
        float2* dst1 = g_Xf[2 * r];
        float2* dst2 = g_Xf[2 * r + 1];
        const float scale = 0.5f / (float)NN;
#pragma unroll
        for (int k = 0; k < 16; ++k) {
            const int n   = tid + 256 * k;
            const int sg  = (1 - n) & (NN - 1);    // shifted reversal
            const float2 z  = v[SW16(k)];
            const float2 ws = b0[PIDX16(sg)];
            dst1[n] = make_float2(scale * (z.x + ws.x), scale * (z.y - ws.y));
            dst2[n] = make_float2(scale * (z.y + ws.y), scale * (ws.x - z.x));
        }
    }
}

// ===================== K2: main (one (j,b) per block) =======================

// e^{i*pi*k/16}
__device__ __constant__ float E16C[16] = { 1.0f, 0.98078528040323044913f,
    0.92387953251128675613f, 0.83146961230254523708f, 0.70710678118654752440f,
    0.55557023301960222474f, 0.38268343236508977172f, 0.19509032201612826785f,
    0.0f, -0.19509032201612826785f, -0.38268343236508977172f,
    -0.55557023301960222474f, -0.70710678118654752440f, -0.83146961230254523708f,
    -0.92387953251128675613f, -0.98078528040323044913f };
__device__ __constant__ float E16S[16] = { 0.0f, 0.19509032201612826785f,
    0.38268343236508977172f, 0.55557023301960222474f, 0.70710678118654752440f,
    0.83146961230254523708f, 0.92387953251128675613f, 0.98078528040323044913f,
    1.0f, 0.98078528040323044913f, 0.92387953251128675613f,
    0.83146961230254523708f, 0.70710678118654752440f, 0.55557023301960222474f,
    0.38268343236508977172f, 0.19509032201612826785f };

__global__ void __launch_bounds__(NT, 1) ldr_main_kernel(float* __restrict__ out)
{
    extern __shared__ float2 smem2[];
    float2* b0 = smem2;
    float2* b1 = smem2 + NPAD16;
    float2* sH = smem2 + 2 * NPAD16;      // staged Hz of current chain (c>=1)
    float2* sG = sH + NN;                 // staged Gz of current chain
    float2* sX = sG + NN;                 // staged Xf of current pair (c>=2)
    const int tid = threadIdx.x;
    float2 wA, wB, d0;
    { float s, c; sincospif((float)tid * (1.0f / 2048.0f), &s, &c);         wA = make_float2(c, -s); }
    { float s, c; sincospif((float)(tid & ~15) * (1.0f / 2048.0f), &s, &c); wB = make_float2(c, -s); }
    { float s, c; sincospif((float)tid * (1.0f / 4096.0f), &s, &c);         d0 = make_float2(c,  s); }

    const int j = blockIdx.x >> 5;
    const int b = blockIdx.x & 31;

    float2 acc[16];
#pragma unroll
    for (int k = 0; k < 16; ++k) acc[k] = make_float2(0.0f, 0.0f);

    // 8 chains: chain c -> i = c>>1, sp = c&1; pair row pr = (i*COUT+j)*2+sp.
    // Buffer parity alternates per chain: even A=b0, odd A=b1.
#pragma unroll 1
    for (int c = 0; c < 8; ++c) {
        const int i  = c >> 1, sp = c & 1;
        const int pr = (i * COUT + j) * 2 + sp;
        const float2* __restrict__ hz = (c == 0) ? g_Hz[pr] : sH;
        const float2* __restrict__ xf = (c < 2)  ? g_Xf[i * BATCH + b] : sX;
        float2* A = (c & 1) ? b1 : b0;
        float2* B = (c & 1) ? b0 : b1;

        float2 v[16];
#pragma unroll
        for (int k = 0; k < 16; ++k) {
            const int n = tid + 256 * k;
            v[k] = cmul(hz[n], xf[n]);                  // u1 + i*u2
        }
        // fft #1
        stage_store16<0,0>(v, A, wA, tid, 0);
        __syncthreads();                                   // bar1
        // prefetches (post-barrier: pack reads + prior accumulate done):
        //   Gz of THIS chain (used after bar5), Hz of NEXT chain (next pack),
        //   Xf of next pair (when i changes).
        {
            prefetch_row(sG, g_Gz[pr], tid);
            if (c < 7) {
                const int cn  = c + 1;
                const int prn = ((cn >> 1) * COUT + j) * 2 + (cn & 1);
                prefetch_row(sH, g_Hz[prn], tid);
                if (c & 1) prefetch_row(sX, g_Xf[(cn >> 1) * BATCH + b], tid);
            }
            cp_commit();
        }
        stage_load16(v, A, tid);
        stage_store16<0,0>(v, B, wB, tid, 4);
        __syncthreads();                                   // bar2
        stage_load16(v, B, tid);
        dft16A<0>(v);                                      // swapped
        // D multiply in swapped slots: slot m holds n = tid + 256*SW16(m)
#pragma unroll
        for (int m = 0; m < 16; ++m)
            v[m] = cmul(v[m], cmul(d0, make_float2(E16C[SW16(m)], E16S[SW16(m)])));
        // fft #2 (input swapped)
        stage_store16<0,1>(v, A, wA, tid, 0);
        __syncthreads();                                   // bar3
        stage_load16(v, A, tid);
        stage_store16<0,0>(v, B, wB, tid, 4);
        __syncthreads();                                   // bar4
        stage_load16(v, B, tid);
        dft16A<0>(v);                                      // swapped
        // Hermitian unpack through A
#pragma unroll
        for (int k = 0; k < 16; ++k) A[PIDX16(tid + 256 * k)] = v[SW16(k)];
        cp_wait_all();            // staging done before bar5 -> visible after
        __syncthreads();                                   // bar5
        // acc[n] += Wv[n]*conj(Gz[rev]) + conj(Wv[rev])*Gz[n]
#pragma unroll
        for (int k = 0; k < 16; ++k) {
            const int n   = tid + 256 * k;
            const int rev = (NN - n) & (NN - 1);
            const float2 ws = A[PIDX16(rev)];              // Wv[rev]
            const float2 vk = v[SW16(k)];                  // Wv[n]
            const float2 gz = sG[n];
            const float2 gr = sG[rev];
            acc[k] = cadd(acc[k], cadd(cmulcj(vk, gr), cmulcj(gz, ws)));
        }
    }

    // final IFFT of acc. Chain 7 (A=b1): b0's last reads pre-unpack-barrier,
    // so storing b0 first is one-barrier separated.
    stage_store16<1,0>(acc, b0, wA, tid, 0);
    __syncthreads();
    stage_load16(acc, b0, tid);
    stage_store16<1,0>(acc, b1, wB, tid, 4);
    __syncthreads();
    stage_load16(acc, b1, tid);
    dft16A<1>(acc);                                    // swapped
    float* op = out + (j * BATCH + b) * NN;
    const float inv = 1.0f / (2.0f * (float)NN);
#pragma unroll
    for (int k = 0; k < 16; ++k) op[tid + 256 * k] = acc[SW16(k)].x * inv;
}

extern "C" void kernel_launch(void* const* d_in, const int* in_sizes, int n_in,
                              void* d_out, int out_size)
{
    const float* x = (const float*)d_in[0];   // (4, 32, 4096)
    const float* G = (const float*)d_in[1];   // (4, 4, 4, 4096)
    const float* H = (const float*)d_in[2];   // (4, 4, 4, 4096)
    float* out = (float*)d_out;               // (4, 32, 4096)

    cudaFuncSetAttribute(ldr_prep_kernel, cudaFuncAttributeMaxDynamicSharedMemorySize, PREP_SMEM);
    cudaFuncSetAttribute(ldr_main_kernel, cudaFuncAttributeMaxDynamicSharedMemorySize, MAIN_SMEM);

    ldr_prep_kernel<<<128, NT, PREP_SMEM>>>(x, G, H);
    ldr_main_kernel<<<128, NT, MAIN_SMEM>>>(out);
}

// round 17
// speedup vs baseline: 2.0481x; 1.1309x over previous
#include <cuda_runtime.h>

// LDR toeplitz-displacement layer via FFT, fully packed form.
//   Hz = fft(D*(h1+i*h2))  (= Hf1 + i*Hf2, raw)    [32 rows]
//   Gz = fft(g1+i*g2)      (= Gf1 + i*Gf2, raw)    [32 rows]
//   Xf = ifft(conj(D)*x)   (real-unpacked, true)   [128 rows]
// Chain (pair of terms): z = Hz.Xf ; Wv = fft(D.fft(z)).
// KEY IDENTITY (R17): with S[n] = Wv[n]*conj(Gz[(N-n)%N]),
//   Gf.Tf sum = (S + conj(S o rev))/2 and Re(ifft(conj(S o rev))) = Re(ifft(S))
//   => out = Re(invDFT(sum_chains S)) / N.   No Wv-reversal exchange needed:
//   Wv stays in registers, accumulate is one cmul-conj per element.
// Main: radix-16 Stockham (2 smem exchanges), in-place digit-swapped DFT16,
// register twiddles (w1..w8 hybrid) from 2 per-thread bases (no W table),
// cp.async staging of sG (this chain), sH (next chain), sX (next pair),
// issued after bar1 / waited before bar4. 4 barriers per chain (was 5).
// Uniform buffers A=b0,B=b1 every chain (hazards re-audited barrier-by-barrier).

#define NN    4096
#define CIN   4
#define COUT  4
#define RANK  4
#define BATCH 32

#define NT    256
#define PIDX16(i) ((i) + ((i) >> 4))
#define NPAD16 4352
#define PREP_SMEM ((2 * NPAD16) * (int)sizeof(float2))
// main: b0 b1 + staging sH[NN] sG[NN] sX[NN]
#define MAIN_SMEM ((2 * NPAD16 + 3 * NN) * (int)sizeof(float2))

#define SW16(m) ((((m) & 3) << 2) | ((m) >> 2))

__device__ float2 g_Hz[CIN*COUT*RANK/2][NN];   // 1 MB
__device__ float2 g_Gz[CIN*COUT*RANK/2][NN];   // 1 MB
__device__ float2 g_Xf[CIN*BATCH][NN];         // 4 MB

__device__ __forceinline__ float2 cmul(float2 a, float2 b) {
    return make_float2(a.x*b.x - a.y*b.y, a.x*b.y + a.y*b.x);
}
__device__ __forceinline__ float2 cadd(float2 a, float2 b) { return make_float2(a.x+b.x, a.y+b.y); }
__device__ __forceinline__ float2 csub(float2 a, float2 b) { return make_float2(a.x-b.x, a.y-b.y); }
// a * conj(b)
__device__ __forceinline__ float2 cmulcj(float2 a, float2 b) {
    return make_float2(a.x*b.x + a.y*b.y, a.y*b.x - a.x*b.y);
}

// ---- cp.async helpers ----
__device__ __forceinline__ void cp16(float2* smem_dst, const float2* gsrc) {
    unsigned saddr = (unsigned)__cvta_generic_to_shared(smem_dst);
    asm volatile("cp.async.cg.shared.global [%0], [%1], 16;\n" :: "r"(saddr), "l"(gsrc));
}
__device__ __forceinline__ void cp_commit() {
    asm volatile("cp.async.commit_group;\n" ::: "memory");
}
__device__ __forceinline__ void cp_wait_all() {
    asm volatile("cp.async.wait_group 0;\n" ::: "memory");
}
__device__ __forceinline__ void prefetch_row(float2* dst, const float2* src, int tid) {
#pragma unroll
    for (int i = 0; i < 8; ++i) {
        const int o = 2 * (tid + 256 * i);
        cp16(dst + o, src + o);
    }
}

// ============ radix-16 machinery (in-place digit-swapped DFT16) =============

template<int INV>
__device__ __forceinline__ void dft4ip(float2& a, float2& b, float2& c, float2& d) {
    float2 t0 = cadd(a,c), t1 = csub(a,c), t2 = cadd(b,d), bd = csub(b,d);
    float2 t3 = INV ? make_float2(-bd.y, bd.x) : make_float2(bd.y, -bd.x);
    a = cadd(t0,t2); b = cadd(t1,t3); c = csub(t0,t2); d = csub(t1,t3);
}

template<int INV>
__device__ __forceinline__ void tw16ip(float2 v[16]) {
    const float C1 = 0.92387953251128675613f;
    const float S1 = 0.38268343236508977172f;
    const float CC = 0.70710678118654752440f;
#define TW(m, c, s) v[m] = cmul(v[m], make_float2((c), INV ? (s) : -(s)))
    TW(5,  C1,  S1);
    TW(6,  CC,  CC);
    TW(7,  S1,  C1);
    TW(9,  CC,  CC);
    TW(10, 0.0f, 1.0f);
    TW(11, -CC, CC);
    TW(13, S1,  C1);
    TW(14, -CC, CC);
    TW(15, -C1, -S1);
#undef TW
}

template<int INV>
__device__ __forceinline__ void dft16A(float2 v[16]) {
#pragma unroll
    for (int n0 = 0; n0 < 4; ++n0) dft4ip<INV>(v[n0], v[n0+4], v[n0+8], v[n0+12]);
    tw16ip<INV>(v);
#pragma unroll
    for (int q = 0; q < 4; ++q) dft4ip<INV>(v[4*q], v[4*q+1], v[4*q+2], v[4*q+3]);
}

template<int INV>
__device__ __forceinline__ void dft16B(float2 v[16]) {
#pragma unroll
    for (int q = 0; q < 4; ++q) dft4ip<INV>(v[4*q], v[4*q+1], v[4*q+2], v[4*q+3]);
    tw16ip<INV>(v);
#pragma unroll
    for (int n0 = 0; n0 < 4; ++n0) dft4ip<INV>(v[n0], v[n0+4], v[n0+8], v[n0+12]);
}

// butterfly + hybrid twiddle scatter. w1raw = W4096^{k1} (forward; conj if INV)
template<int INV, int IN_SWAPPED>
__device__ __forceinline__ void stage_store16(float2 v[16], float2* __restrict__ sb,
                                              float2 w1raw, int u, int sshift) {
    if (IN_SWAPPED) dft16B<INV>(v); else dft16A<INV>(v);
    const int s  = 1 << sshift;
    const int k1 = u & ~(s - 1);
    const int base = u + 15 * k1;
    float2 w1 = w1raw;
    if (INV) w1.y = -w1.y;
    const float2 w2 = cmul(w1, w1);
    const float2 w3 = cmul(w2, w1);
    const float2 w4 = cmul(w2, w2);
    const float2 w5 = cmul(w4, w1);
    const float2 w6 = cmul(w4, w2);
    const float2 w7 = cmul(w4, w3);
    const float2 w8 = cmul(w4, w4);
    const float2 wlo[8] = { make_float2(1.0f, 0.0f), w1, w2, w3, w4, w5, w6, w7 };
#pragma unroll
    for (int k = 0; k < 16; ++k) {
        float2 o = IN_SWAPPED ? v[k] : v[SW16(k)];
        if (k >= 8) o = cmul(o, w8);
        if (k & 7)  o = cmul(o, wlo[k & 7]);
        sb[PIDX16(base + k * s)] = o;
    }
}

__device__ __forceinline__ void stage_load16(float2 v[16], const float2* __restrict__ sb, int tid) {
#pragma unroll
    for (int k = 0; k < 16; ++k) v[k] = sb[PIDX16(tid + 256 * k)];
}

// ================ K1: prep =================================================
// bid<32: Hz[bid] = fft(D*(h1+i*h2)) raw. 32<=bid<64: Gz raw.
// 64<=bid<128: Xf pair = ifft(conj(D)*x) with real unpack + 1/N.

__global__ void __launch_bounds__(NT, 2) ldr_prep_kernel(const float* __restrict__ x,
                                                         const float* __restrict__ G,
                                                         const float* __restrict__ H)
{
    extern __shared__ float2 smem2[];
    float2* b0 = smem2;
    float2* b1 = smem2 + NPAD16;
    const int tid = threadIdx.x;
    float2 wA, wB;
    { float s, c; sincospif((float)tid * (1.0f / 2048.0f), &s, &c);         wA = make_float2(c, -s); }
    { float s, c; sincospif((float)(tid & ~15) * (1.0f / 2048.0f), &s, &c); wB = make_float2(c, -s); }

    const int bid = blockIdx.x;
    float2 v[16];

    if (bid < 64) {
        float2* dst;
        if (bid < 32) {      // Hz: D * (h1 + i h2)
            const float* h1 = H + (2 * bid) * NN;
            const float* h2 = H + (2 * bid + 1) * NN;
#pragma unroll
            for (int k = 0; k < 16; ++k) {
                const int n = tid + 256 * k;
                float s, c; sincospif((float)n * (1.0f / 4096.0f), &s, &c);
                v[k] = cmul(make_float2(c, s), make_float2(h1[n], h2[n]));
            }
            dst = g_Hz[bid];
        } else {             // Gz: g1 + i g2
            const int r = bid - 32;
            const float* g1 = G + (2 * r) * NN;
            const float* g2 = G + (2 * r + 1) * NN;
#pragma unroll
            for (int k = 0; k < 16; ++k) {
                const int n = tid + 256 * k;
                v[k] = make_float2(g1[n], g2[n]);
            }
            dst = g_Gz[r];
        }
        stage_store16<0,0>(v, b0, wA, tid, 0);
        __syncthreads();
        stage_load16(v, b0, tid);
        stage_store16<0,0>(v, b1, wB, tid, 4);
        __syncthreads();
        stage_load16(v, b1, tid);
        dft16A<0>(v);                      // swapped
#pragma unroll
        for (int k = 0; k < 16; ++k) dst[tid + 256 * k] = v[SW16(k)];
    } else {
        // Xf pair: inverse + shifted-Hermitian unpack, scale 0.5/N
        const int r = bid - 64;
        const float* x1 = x + (2 * r) * NN;
        const float* x2 = x + (2 * r + 1) * NN;
#pragma unroll
        for (int k = 0; k < 16; ++k) {
            const int n = tid + 256 * k;
            float s, c; sincospif((float)n * (1.0f / 4096.0f), &s, &c);
            v[k] = cmul(make_float2(c, -s), make_float2(x1[n], x2[n]));
        }
        stage_store16<1,0>(v, b0, wA, tid, 0);
        __syncthreads();
        stage_load16(v, b0, tid);
        stage_store16<1,0>(v, b1, wB, tid, 4);
        __syncthreads();
        stage_load16(v, b1, tid);
        dft16A<1>(v);                      // swapped
#pragma unroll
        for (int k = 0; k < 16; ++k) b0[PIDX16(tid + 256 * k)] = v[SW16(k)];
        __syncthreads();
        float2* dst1 = g_Xf[2 * r];
        float2* dst2 = g_Xf[2 * r + 1];
        const float scale = 0.5f / (float)NN;
#pragma unroll
        for (int k = 0; k < 16; ++k) {
            const int n   = tid + 256 * k;
            const int sg  = (1 - n) & (NN - 1);    // shifted reversal
            const float2 z  = v[SW16(k)];
            const float2 ws = b0[PIDX16(sg)];
            dst1[n] = make_float2(scale * (z.x + ws.x), scale * (z.y - ws.y));
            dst2[n] = make_float2(scale * (z.y + ws.y), scale * (ws.x - z.x));
        }
    }
}

// ===================== K2: main (one (j,b) per block) =======================

// e^{i*pi*k/16}
__device__ __constant__ float E16C[16] = { 1.0f, 0.98078528040323044913f,
    0.92387953251128675613f, 0.83146961230254523708f, 0.70710678118654752440f,
    0.55557023301960222474f, 0.38268343236508977172f, 0.19509032201612826785f,
    0.0f, -0.19509032201612826785f, -0.38268343236508977172f,
    -0.55557023301960222474f, -0.70710678118654752440f, -0.83146961230254523708f,
    -0.92387953251128675613f, -0.98078528040323044913f };
__device__ __constant__ float E16S[16] = { 0.0f, 0.19509032201612826785f,
    0.38268343236508977172f, 0.55557023301960222474f, 0.70710678118654752440f,
    0.83146961230254523708f, 0.92387953251128675613f, 0.98078528040323044913f,
    1.0f, 0.98078528040323044913f, 0.92387953251128675613f,
    0.83146961230254523708f, 0.70710678118654752440f, 0.55557023301960222474f,
    0.38268343236508977172f, 0.19509032201612826785f };

__global__ void __launch_bounds__(NT, 1) ldr_main_kernel(float* __restrict__ out)
{
    extern __shared__ float2 smem2[];
    float2* b0 = smem2;
    float2* b1 = smem2 + NPAD16;
    float2* sH = smem2 + 2 * NPAD16;      // staged Hz of current chain (c>=1)
    float2* sG = sH + NN;                 // staged Gz of current chain
    float2* sX = sG + NN;                 // staged Xf of current pair (c>=2)
    const int tid = threadIdx.x;
    float2 wA, wB, d0;
    { float s, c; sincospif((float)tid * (1.0f / 2048.0f), &s, &c);         wA = make_float2(c, -s); }
    { float s, c; sincospif((float)(tid & ~15) * (1.0f / 2048.0f), &s, &c); wB = make_float2(c, -s); }
    { float s, c; sincospif((float)tid * (1.0f / 4096.0f), &s, &c);         d0 = make_float2(c,  s); }

    const int j = blockIdx.x >> 5;
    const int b = blockIdx.x & 31;

    float2 acc[16];
#pragma unroll
    for (int k = 0; k < 16; ++k) acc[k] = make_float2(0.0f, 0.0f);

    // 8 chains: chain c -> i = c>>1, sp = c&1; pair row pr = (i*COUT+j)*2+sp.
    // Uniform buffers A=b0, B=b1 (hazard audit in header). 4 barriers/chain.
#pragma unroll 1
    for (int c = 0; c < 8; ++c) {
        const int i  = c >> 1, sp = c & 1;
        const int pr = (i * COUT + j) * 2 + sp;
        const float2* __restrict__ hz = (c == 0) ? g_Hz[pr] : sH;
        const float2* __restrict__ xf = (c < 2)  ? g_Xf[i * BATCH + b] : sX;

        float2 v[16];
#pragma unroll
        for (int k = 0; k < 16; ++k) {
            const int n = tid + 256 * k;
            v[k] = cmul(hz[n], xf[n]);                  // u1 + i*u2
        }
        // fft #1
        stage_store16<0,0>(v, b0, wA, tid, 0);
        __syncthreads();                                   // bar1
        // prefetches (post-barrier: pack + prior accumulate reads done):
        //   Gz of THIS chain (used after bar4), Hz of NEXT chain (next pack),
        //   Xf of next pair (when i changes).
        {
            prefetch_row(sG, g_Gz[pr], tid);
            if (c < 7) {
                const int cn  = c + 1;
                const int prn = ((cn >> 1) * COUT + j) * 2 + (cn & 1);
                prefetch_row(sH, g_Hz[prn], tid);
                if (c & 1) prefetch_row(sX, g_Xf[(cn >> 1) * BATCH + b], tid);
            }
            cp_commit();
        }
        stage_load16(v, b0, tid);
        stage_store16<0,0>(v, b1, wB, tid, 4);
        __syncthreads();                                   // bar2
        stage_load16(v, b1, tid);
        dft16A<0>(v);                                      // swapped
        // D multiply in swapped slots: slot m holds n = tid + 256*SW16(m)
#pragma unroll
        for (int m = 0; m < 16; ++m)
            v[m] = cmul(v[m], cmul(d0, make_float2(E16C[SW16(m)], E16S[SW16(m)])));
        // fft #2 (input swapped)
        stage_store16<0,1>(v, b0, wA, tid, 0);
        __syncthreads();                                   // bar3
        stage_load16(v, b0, tid);
        stage_store16<0,0>(v, b1, wB, tid, 4);
        cp_wait_all();            // staging lands before bar4 -> visible after
        __syncthreads();                                   // bar4
        stage_load16(v, b1, tid);
        dft16A<0>(v);                                      // swapped: Wv in regs
        // accumulate: acc[n] += Wv[n] * conj(Gz[rev n])   (no Wv exchange!)
#pragma unroll
        for (int k = 0; k < 16; ++k) {
            const int n   = tid + 256 * k;
            const int rev = (NN - n) & (NN - 1);
            acc[k] = cadd(acc[k], cmulcj(v[SW16(k)], sG[rev]));
        }
    }

    // final IFFT of acc. b0's last read was after bar3 of chain 7 -> bar4
    // separates; b1's last read after bar4 -> the barrier below separates.
    stage_store16<1,0>(acc, b0, wA, tid, 0);
    __syncthreads();
    stage_load16(acc, b0, tid);
    stage_store16<1,0>(acc, b1, wB, tid, 4);
    __syncthreads();
    stage_load16(acc, b1, tid);
    dft16A<1>(acc);                                    // swapped
    float* op = out + (j * BATCH + b) * NN;
    const float inv = 1.0f / (float)NN;                // S-form: just 1/N
#pragma unroll
    for (int k = 0; k < 16; ++k) op[tid + 256 * k] = acc[SW16(k)].x * inv;
}

extern "C" void kernel_launch(void* const* d_in, const int* in_sizes, int n_in,
                              void* d_out, int out_size)
{
    const float* x = (const float*)d_in[0];   // (4, 32, 4096)
    const float* G = (const float*)d_in[1];   // (4, 4, 4, 4096)
    const float* H = (const float*)d_in[2];   // (4, 4, 4, 4096)
    float* out = (float*)d_out;               // (4, 32, 4096)

    cudaFuncSetAttribute(ldr_prep_kernel, cudaFuncAttributeMaxDynamicSharedMemorySize, PREP_SMEM);
    cudaFuncSetAttribute(ldr_main_kernel, cudaFuncAttributeMaxDynamicSharedMemorySize, MAIN_SMEM);

    ldr_prep_kernel<<<128, NT, PREP_SMEM>>>(x, G, H);
    ldr_main_kernel<<<128, NT, MAIN_SMEM>>>(out);
}